// round 2
// baseline (speedup 1.0000x reference)
#include <cuda_runtime.h>
#include <cuda_bf16.h>
#include <math.h>

// ---------------- problem constants ----------------
#define B_SZ   64
#define T_SZ   32
#define NSTEP  31          // T-1 decode steps
#define EMB    300
#define FEAT   4100        // 2048 + 2052
#define HID    512
#define G3     1536        // 3*HID
#define VOCAB  32000
#define MROWS  1984        // B*NSTEP

// ---------------- device scratch (no allocation allowed) ----------------
__device__ float g_wihT[EMB * G3];     // [300][1536]
__device__ float g_whhT[HID * G3];     // [512][1536]
__device__ float g_xg[MROWS * G3];     // [m=b*31+t][1536]
__device__ float g_h[2][B_SZ * HID];   // ping-pong hidden state
__device__ float g_hs[MROWS * HID];    // [m][512]

// ---------------- f32x2 helpers (ptxas won't auto-fuse; must use PTX) ---
__device__ __forceinline__ void fma2(unsigned long long& d,
                                     unsigned long long a,
                                     unsigned long long b) {
    asm("fma.rn.f32x2 %0, %1, %2, %0;" : "+l"(d) : "l"(a), "l"(b));
}
__device__ __forceinline__ unsigned long long pack2(float x) {
    unsigned long long r;
    asm("mov.b64 %0, {%1, %2};" : "=l"(r) : "f"(x), "f"(x));
    return r;
}
__device__ __forceinline__ void unpack2(unsigned long long d, float& lo, float& hi) {
    asm("mov.b64 {%0, %1}, %2;" : "=f"(lo), "=f"(hi) : "l"(d));
}

// ---------------- weight transposes (w_ih, w_hh -> K-major) -------------
__global__ void transpose_weights(const float* __restrict__ w_ih,
                                  const float* __restrict__ w_hh) {
    int idx = blockIdx.x * 256 + threadIdx.x;
    const int N1 = EMB * G3;          // 460800
    const int NT = N1 + HID * G3;     // + 786432
    if (idx < N1) {
        int k = idx / G3, g = idx - k * G3;
        g_wihT[idx] = w_ih[g * EMB + k];
    } else if (idx < NT) {
        int r = idx - N1;
        int k = r / G3, g = r - k * G3;
        g_whhT[r] = w_hh[g * HID + k];
    }
}

// ---------------- generic 128x128 tiled GEMM, C = A*B + bias ------------
// A: [M,K] row-major (a_mode==1: row m maps to word_embs row (m/31*32+m%31))
// B: [K,N] row-major.  256 threads, 8x8 micro-tile, f32x2 FMAs.
__global__ __launch_bounds__(256)
void gemm128(const float* __restrict__ A, const float* __restrict__ Bm,
             const float* __restrict__ bias, float* __restrict__ C,
             int M, int N, int K, int a_mode) {
    __shared__ __align__(16) float As[16][132];
    __shared__ __align__(16) float Bs[16][128];
    int tid = threadIdx.x;
    int mtile = blockIdx.y * 128;
    int ntile = blockIdx.x * 128;
    int tm = tid >> 4, tn = tid & 15;
    int m0 = tm * 8, n0 = tn * 8;

    unsigned long long acc[8][4];
#pragma unroll
    for (int i = 0; i < 8; i++)
#pragma unroll
        for (int j = 0; j < 4; j++) acc[i][j] = 0ull;

    int nchunks = (K + 15) >> 4;
    for (int c = 0; c < nchunks; c++) {
        int kc = c << 4;
        // A tile -> As (transposed)
#pragma unroll
        for (int q = 0; q < 2; q++) {
            int id  = tid * 2 + q;          // 0..511
            int row = id >> 2;              // 0..127
            int kq  = (id & 3) * 4;         // 0,4,8,12
            int m   = mtile + row;
            float4 v = make_float4(0.f, 0.f, 0.f, 0.f);
            if (m < M) {
                long roff;
                if (a_mode) { int bb = m / 31; int tt = m - bb * 31;
                              roff = (long)(bb * 32 + tt) * K; }
                else roff = (long)m * K;
                int k = kc + kq;
                if (k + 3 < K) {
                    v = *(const float4*)(A + roff + k);
                } else {
                    float tmp[4] = {0.f, 0.f, 0.f, 0.f};
#pragma unroll
                    for (int u = 0; u < 4; u++)
                        if (k + u < K) tmp[u] = A[roff + k + u];
                    v = make_float4(tmp[0], tmp[1], tmp[2], tmp[3]);
                }
            }
            As[kq + 0][row] = v.x; As[kq + 1][row] = v.y;
            As[kq + 2][row] = v.z; As[kq + 3][row] = v.w;
        }
        // B tile -> Bs
#pragma unroll
        for (int q = 0; q < 2; q++) {
            int id = tid + q * 256;         // 0..511
            int r  = id >> 5;               // 0..15
            int nq = (id & 31) * 4;         // 0..124
            int k  = kc + r;
            float4 v = make_float4(0.f, 0.f, 0.f, 0.f);
            if (k < K) v = *(const float4*)(Bm + (long)k * N + ntile + nq);
            *(float4*)&Bs[r][nq] = v;
        }
        __syncthreads();
#pragma unroll
        for (int kk = 0; kk < 16; kk++) {
            float4 a0 = *(const float4*)&As[kk][m0];
            float4 a1 = *(const float4*)&As[kk][m0 + 4];
            const unsigned long long* bp =
                (const unsigned long long*)&Bs[kk][n0];
            unsigned long long b2[4] = {bp[0], bp[1], bp[2], bp[3]};
            float av[8] = {a0.x, a0.y, a0.z, a0.w, a1.x, a1.y, a1.z, a1.w};
#pragma unroll
            for (int i = 0; i < 8; i++) {
                unsigned long long ai = pack2(av[i]);
#pragma unroll
                for (int j = 0; j < 4; j++) fma2(acc[i][j], ai, b2[j]);
            }
        }
        __syncthreads();
    }
    // epilogue
    float bvals[8];
#pragma unroll
    for (int j = 0; j < 8; j++) bvals[j] = bias[ntile + n0 + j];
#pragma unroll
    for (int i = 0; i < 8; i++) {
        int m = mtile + m0 + i;
        if (m < M) {
            float* crow = C + (long)m * N + ntile + n0;
#pragma unroll
            for (int j = 0; j < 4; j++) {
                float lo, hi; unpack2(acc[i][j], lo, hi);
                crow[2 * j]     = lo + bvals[2 * j];
                crow[2 * j + 1] = hi + bvals[2 * j + 1];
            }
        }
    }
}

// ---------------- h0 = relu(concat(vis,tof) @ W_map + b_map) ------------
// grid 64 (j-tiles of 8), 256 threads = 4 K-groups x (8 b-groups x 8 j)
__global__ __launch_bounds__(256)
void h0_kernel(const float* __restrict__ vis, const float* __restrict__ tof,
               const float* __restrict__ W_map, const float* __restrict__ b_map,
               float* __restrict__ h_out) {
    __shared__ __align__(16) float fT[64][66];
    __shared__ float ws[64][8];
    __shared__ float red[4][64][8];
    int tid = threadIdx.x;
    int kg = tid >> 6;
    int inner = tid & 63;
    int bg = inner >> 3, b0 = bg * 8;
    int jl = inner & 7;
    int j0 = blockIdx.x * 8;
    int j = j0 + jl;

    unsigned long long acc[4] = {0ull, 0ull, 0ull, 0ull};

    for (int kc = 0; kc < FEAT; kc += 64) {
#pragma unroll
        for (int q = 0; q < 16; q++) {
            int id = tid + q * 256;   // 0..4095
            int b = id >> 6, kq = id & 63;
            int f = kc + kq;
            float v = 0.f;
            if (f < 2048) v = vis[b * 2048 + f];
            else if (f < FEAT) v = tof[b * 2052 + (f - 2048)];
            fT[kq][b] = v;
        }
#pragma unroll
        for (int q = 0; q < 2; q++) {
            int id = tid + q * 256;   // 0..511
            int k = id >> 3, jj = id & 7;
            int f = kc + k;
            ws[k][jj] = (f < FEAT) ? W_map[f * HID + j0 + jj] : 0.f;
        }
        __syncthreads();
        int kbase = kg * 16;
#pragma unroll
        for (int i = 0; i < 16; i++) {
            int k = kbase + i;
            unsigned long long w2 = pack2(ws[k][jl]);
#pragma unroll
            for (int p = 0; p < 4; p++) {
                unsigned long long hp =
                    *(const unsigned long long*)&fT[k][b0 + 2 * p];
                fma2(acc[p], w2, hp);
            }
        }
        __syncthreads();
    }
#pragma unroll
    for (int p = 0; p < 4; p++) {
        float lo, hi; unpack2(acc[p], lo, hi);
        red[kg][inner][2 * p] = lo; red[kg][inner][2 * p + 1] = hi;
    }
    __syncthreads();
    if (kg == 0) {
        for (int bi = 0; bi < 8; bi++) {
            int b = b0 + bi;
            float s = 0.f;
#pragma unroll
            for (int g = 0; g < 4; g++) s += red[g][inner][bi];
            s += b_map[j];
            h_out[b * HID + j] = fmaxf(s, 0.f);
        }
    }
}

// ---------------- one fused GRU step ------------------------------------
// grid 64 (j-tiles of 8), 256 threads = 4 K-groups x (8 b-groups x 8 j)
__global__ __launch_bounds__(256)
void gru_step(const float* __restrict__ h_in, float* __restrict__ h_out,
              float* __restrict__ hs, const float* __restrict__ b_hh, int t) {
    __shared__ __align__(16) float hT[64][66];
    __shared__ float ws[64][24];
    __shared__ float red[4][64][24];
    int tid = threadIdx.x;
    int kg = tid >> 6;
    int inner = tid & 63;
    int bg = inner >> 3, b0 = bg * 8;
    int jl = inner & 7;
    int j0 = blockIdx.x * 8;
    int j = j0 + jl;

    unsigned long long ar[4] = {0ull,0ull,0ull,0ull};
    unsigned long long az[4] = {0ull,0ull,0ull,0ull};
    unsigned long long an[4] = {0ull,0ull,0ull,0ull};

    for (int kc = 0; kc < HID; kc += 64) {
#pragma unroll
        for (int q = 0; q < 4; q++) {
            int id = tid + q * 256;   // 0..1023 float4 ids
            int b = id >> 4;
            int kq = (id & 15) * 4;
            float4 v = *(const float4*)(h_in + b * HID + kc + kq);
            hT[kq + 0][b] = v.x; hT[kq + 1][b] = v.y;
            hT[kq + 2][b] = v.z; hT[kq + 3][b] = v.w;
        }
#pragma unroll
        for (int q = 0; q < 6; q++) {
            int id = tid + q * 256;   // 0..1535
            int k = id / 24, c = id - k * 24;
            int gate = c >> 3, jj = c & 7;
            ws[k][c] = g_whhT[(kc + k) * G3 + gate * HID + j0 + jj];
        }
        __syncthreads();
        int kbase = kg * 16;
#pragma unroll
        for (int i = 0; i < 16; i++) {
            int k = kbase + i;
            unsigned long long wr = pack2(ws[k][jl]);
            unsigned long long wz = pack2(ws[k][8 + jl]);
            unsigned long long wn = pack2(ws[k][16 + jl]);
#pragma unroll
            for (int p = 0; p < 4; p++) {
                unsigned long long hp =
                    *(const unsigned long long*)&hT[k][b0 + 2 * p];
                fma2(ar[p], wr, hp);
                fma2(az[p], wz, hp);
                fma2(an[p], wn, hp);
            }
        }
        __syncthreads();
    }
    float* rp = &red[kg][inner][0];
#pragma unroll
    for (int p = 0; p < 4; p++) {
        float lo, hi;
        unpack2(ar[p], lo, hi); rp[2*p] = lo;      rp[2*p+1] = hi;
        unpack2(az[p], lo, hi); rp[8+2*p] = lo;    rp[8+2*p+1] = hi;
        unpack2(an[p], lo, hi); rp[16+2*p] = lo;   rp[16+2*p+1] = hi;
    }
    __syncthreads();
    if (kg == 0) {
        for (int bi = 0; bi < 8; bi++) {
            int b = b0 + bi;
            float sr = 0.f, sz = 0.f, sn = 0.f;
#pragma unroll
            for (int g = 0; g < 4; g++) {
                sr += red[g][inner][bi];
                sz += red[g][inner][8 + bi];
                sn += red[g][inner][16 + bi];
            }
            sr += b_hh[j]; sz += b_hh[HID + j]; sn += b_hh[2 * HID + j];
            const float* xrow = g_xg + ((long)b * NSTEP + t) * G3;
            float r = 1.f / (1.f + expf(-(xrow[j] + sr)));
            float z = 1.f / (1.f + expf(-(xrow[HID + j] + sz)));
            float n = tanhf(xrow[2 * HID + j] + r * sn);
            float hp = h_in[b * HID + j];
            float hn = (1.f - z) * n + z * hp;
            h_out[b * HID + j] = hn;
            hs[((long)b * NSTEP + t) * HID + j] = hn;
        }
    }
}

// ---------------- launch ----------------
extern "C" void kernel_launch(void* const* d_in, const int* in_sizes, int n_in,
                              void* d_out, int out_size) {
    const float* word_embs = (const float*)d_in[0];
    const float* vis       = (const float*)d_in[1];
    const float* tof       = (const float*)d_in[2];
    // d_in[3] = lang_len (int64) unused by reference computation
    const float* W_map     = (const float*)d_in[4];
    const float* b_map     = (const float*)d_in[5];
    const float* w_ih      = (const float*)d_in[6];
    const float* w_hh      = (const float*)d_in[7];
    const float* b_ih      = (const float*)d_in[8];
    const float* b_hh      = (const float*)d_in[9];
    const float* W_cls     = (const float*)d_in[10];
    const float* b_cls     = (const float*)d_in[11];
    float* out = (float*)d_out;

    float *wihT, *whhT, *xg, *h, *hs;
    cudaGetSymbolAddress((void**)&wihT, g_wihT);
    cudaGetSymbolAddress((void**)&whhT, g_whhT);
    cudaGetSymbolAddress((void**)&xg,   g_xg);
    cudaGetSymbolAddress((void**)&h,    g_h);
    cudaGetSymbolAddress((void**)&hs,   g_hs);

    // 1) transpose GRU weights to K-major
    {
        int total = EMB * G3 + HID * G3;
        transpose_weights<<<(total + 255) / 256, 256>>>(w_ih, w_hh);
    }
    // 2) h0
    h0_kernel<<<64, 256>>>(vis, tof, W_map, b_map, h /* g_h[0] */);
    // 3) x_gates = word_embs[:, :31] @ w_ih^T + b_ih  -> g_xg[m][1536]
    {
        dim3 grid(G3 / 128, (MROWS + 127) / 128);
        gemm128<<<grid, 256>>>(word_embs, wihT, b_ih, xg,
                               MROWS, G3, EMB, /*a_mode=*/1);
    }
    // 4) 31 sequential GRU steps (ping-pong hidden state)
    for (int t = 0; t < NSTEP; t++) {
        const float* hin = h + (t & 1) * (B_SZ * HID);
        float* hout      = h + ((t + 1) & 1) * (B_SZ * HID);
        gru_step<<<64, 256>>>(hin, hout, hs, b_hh, t);
    }
    // 5) classifier: logits = hs @ W_cls + b_cls -> d_out [1984, 32000]
    {
        dim3 grid(VOCAB / 128, (MROWS + 127) / 128);
        gemm128<<<grid, 256>>>(hs, W_cls, b_cls, out,
                               MROWS, VOCAB, HID, /*a_mode=*/0);
    }
    (void)in_sizes; (void)n_in; (void)out_size;
}

// round 3
// speedup vs baseline: 1.4876x; 1.4876x over previous
#include <cuda_runtime.h>
#include <cuda_bf16.h>
#include <math.h>

// ---------------- problem constants ----------------
#define B_SZ   64
#define T_SZ   32
#define NSTEP  31          // T-1 decode steps
#define EMB    300
#define FEAT   4100        // 2048 + 2052
#define HID    512
#define G3     1536        // 3*HID
#define VOCAB  32000
#define MROWS  1984        // B*NSTEP

// ---------------- device scratch (no allocation allowed) ----------------
__device__ float g_wihT[EMB * G3];     // [300][1536]
__device__ float g_whhT[HID * G3];     // [512][1536]
__device__ float g_xg[MROWS * G3];     // [m=b*31+t][1536]
__device__ float g_h[2][B_SZ * HID];   // ping-pong hidden state
__device__ float g_hs[MROWS * HID];    // [m][512]

// ---------------- f32x2 helpers (ptxas won't auto-fuse; must use PTX) ---
__device__ __forceinline__ void fma2(unsigned long long& d,
                                     unsigned long long a,
                                     unsigned long long b) {
    asm("fma.rn.f32x2 %0, %1, %2, %0;" : "+l"(d) : "l"(a), "l"(b));
}
__device__ __forceinline__ unsigned long long pack2(float x) {
    unsigned long long r;
    asm("mov.b64 %0, {%1, %2};" : "=l"(r) : "f"(x), "f"(x));
    return r;
}
__device__ __forceinline__ void unpack2(unsigned long long d, float& lo, float& hi) {
    asm("mov.b64 {%0, %1}, %2;" : "=f"(lo), "=f"(hi) : "l"(d));
}

// ---------------- weight transposes (w_ih, w_hh -> K-major) -------------
__global__ void transpose_weights(const float* __restrict__ w_ih,
                                  const float* __restrict__ w_hh) {
    int idx = blockIdx.x * 256 + threadIdx.x;
    const int N1 = EMB * G3;          // 460800
    const int NT = N1 + HID * G3;     // + 786432
    if (idx < N1) {
        int k = idx / G3, g = idx - k * G3;
        g_wihT[idx] = w_ih[g * EMB + k];
    } else if (idx < NT) {
        int r = idx - N1;
        int k = r / G3, g = r - k * G3;
        g_whhT[r] = w_hh[g * HID + k];
    }
}

// ---------------- generic 128x128 tiled GEMM, C = A*B + bias ------------
// A: [M,K] row-major (a_mode==1: row m maps to word_embs row (m/31*32+m%31))
// B: [K,N] row-major.  256 threads, 8x8 micro-tile, f32x2 FMAs.
__global__ __launch_bounds__(256)
void gemm128(const float* __restrict__ A, const float* __restrict__ Bm,
             const float* __restrict__ bias, float* __restrict__ C,
             int M, int N, int K, int a_mode) {
    __shared__ __align__(16) float As[16][132];
    __shared__ __align__(16) float Bs[16][128];
    int tid = threadIdx.x;
    int mtile = blockIdx.y * 128;
    int ntile = blockIdx.x * 128;
    int tm = tid >> 4, tn = tid & 15;
    int m0 = tm * 8, n0 = tn * 8;

    unsigned long long acc[8][4];
#pragma unroll
    for (int i = 0; i < 8; i++)
#pragma unroll
        for (int j = 0; j < 4; j++) acc[i][j] = 0ull;

    int nchunks = (K + 15) >> 4;
    for (int c = 0; c < nchunks; c++) {
        int kc = c << 4;
        // A tile -> As (transposed)
#pragma unroll
        for (int q = 0; q < 2; q++) {
            int id  = tid * 2 + q;          // 0..511
            int row = id >> 2;              // 0..127
            int kq  = (id & 3) * 4;         // 0,4,8,12
            int m   = mtile + row;
            float4 v = make_float4(0.f, 0.f, 0.f, 0.f);
            if (m < M) {
                long roff;
                if (a_mode) { int bb = m / 31; int tt = m - bb * 31;
                              roff = (long)(bb * 32 + tt) * K; }
                else roff = (long)m * K;
                int k = kc + kq;
                if (k + 3 < K) {
                    v = *(const float4*)(A + roff + k);
                } else {
                    float tmp[4] = {0.f, 0.f, 0.f, 0.f};
#pragma unroll
                    for (int u = 0; u < 4; u++)
                        if (k + u < K) tmp[u] = A[roff + k + u];
                    v = make_float4(tmp[0], tmp[1], tmp[2], tmp[3]);
                }
            }
            As[kq + 0][row] = v.x; As[kq + 1][row] = v.y;
            As[kq + 2][row] = v.z; As[kq + 3][row] = v.w;
        }
        // B tile -> Bs
#pragma unroll
        for (int q = 0; q < 2; q++) {
            int id = tid + q * 256;         // 0..511
            int r  = id >> 5;               // 0..15
            int nq = (id & 31) * 4;         // 0..124
            int k  = kc + r;
            float4 v = make_float4(0.f, 0.f, 0.f, 0.f);
            if (k < K) v = *(const float4*)(Bm + (long)k * N + ntile + nq);
            *(float4*)&Bs[r][nq] = v;
        }
        __syncthreads();
#pragma unroll
        for (int kk = 0; kk < 16; kk++) {
            float4 a0 = *(const float4*)&As[kk][m0];
            float4 a1 = *(const float4*)&As[kk][m0 + 4];
            const unsigned long long* bp =
                (const unsigned long long*)&Bs[kk][n0];
            unsigned long long b2[4] = {bp[0], bp[1], bp[2], bp[3]};
            float av[8] = {a0.x, a0.y, a0.z, a0.w, a1.x, a1.y, a1.z, a1.w};
#pragma unroll
            for (int i = 0; i < 8; i++) {
                unsigned long long ai = pack2(av[i]);
#pragma unroll
                for (int j = 0; j < 4; j++) fma2(acc[i][j], ai, b2[j]);
            }
        }
        __syncthreads();
    }
    // epilogue
    float bvals[8];
#pragma unroll
    for (int j = 0; j < 8; j++) bvals[j] = bias[ntile + n0 + j];
#pragma unroll
    for (int i = 0; i < 8; i++) {
        int m = mtile + m0 + i;
        if (m < M) {
            float* crow = C + (long)m * N + ntile + n0;
#pragma unroll
            for (int j = 0; j < 4; j++) {
                float lo, hi; unpack2(acc[i][j], lo, hi);
                crow[2 * j]     = lo + bvals[2 * j];
                crow[2 * j + 1] = hi + bvals[2 * j + 1];
            }
        }
    }
}

// ---------------- h0 = relu(concat(vis,tof) @ W_map + b_map) ------------
// grid 64 (j-tiles of 8), 256 threads = 4 K-groups x (8 b-groups x 8 j)
__global__ __launch_bounds__(256)
void h0_kernel(const float* __restrict__ vis, const float* __restrict__ tof,
               const float* __restrict__ W_map, const float* __restrict__ b_map,
               float* __restrict__ h_out) {
    __shared__ __align__(16) float fT[64][66];
    __shared__ float ws[64][8];
    __shared__ float red[4][64][8];
    int tid = threadIdx.x;
    int kg = tid >> 6;
    int inner = tid & 63;
    int bg = inner >> 3, b0 = bg * 8;
    int jl = inner & 7;
    int j0 = blockIdx.x * 8;
    int j = j0 + jl;

    unsigned long long acc[4] = {0ull, 0ull, 0ull, 0ull};

    for (int kc = 0; kc < FEAT; kc += 64) {
#pragma unroll
        for (int q = 0; q < 16; q++) {
            int id = tid + q * 256;   // 0..4095
            int b = id >> 6, kq = id & 63;
            int f = kc + kq;
            float v = 0.f;
            if (f < 2048) v = vis[b * 2048 + f];
            else if (f < FEAT) v = tof[b * 2052 + (f - 2048)];
            fT[kq][b] = v;
        }
#pragma unroll
        for (int q = 0; q < 2; q++) {
            int id = tid + q * 256;   // 0..511
            int k = id >> 3, jj = id & 7;
            int f = kc + k;
            ws[k][jj] = (f < FEAT) ? W_map[f * HID + j0 + jj] : 0.f;
        }
        __syncthreads();
        int kbase = kg * 16;
#pragma unroll
        for (int i = 0; i < 16; i++) {
            int k = kbase + i;
            unsigned long long w2 = pack2(ws[k][jl]);
#pragma unroll
            for (int p = 0; p < 4; p++) {
                unsigned long long hp =
                    *(const unsigned long long*)&fT[k][b0 + 2 * p];
                fma2(acc[p], w2, hp);
            }
        }
        __syncthreads();
    }
#pragma unroll
    for (int p = 0; p < 4; p++) {
        float lo, hi; unpack2(acc[p], lo, hi);
        red[kg][inner][2 * p] = lo; red[kg][inner][2 * p + 1] = hi;
    }
    __syncthreads();
    if (kg == 0) {
        for (int bi = 0; bi < 8; bi++) {
            int b = b0 + bi;
            float s = 0.f;
#pragma unroll
            for (int g = 0; g < 4; g++) s += red[g][inner][bi];
            s += b_map[j];
            h_out[b * HID + j] = fmaxf(s, 0.f);
        }
    }
}

// ---------------- one fused GRU step ------------------------------------
// grid 64 (j-tiles of 8), 256 threads = 4 K-groups x (8 b-groups x 8 j)
__global__ __launch_bounds__(256)
void gru_step(const float* __restrict__ h_in, float* __restrict__ h_out,
              float* __restrict__ hs, const float* __restrict__ b_hh, int t) {
    __shared__ __align__(16) float hT[64][66];
    __shared__ float ws[64][24];
    __shared__ float red[4][64][24];
    int tid = threadIdx.x;
    int kg = tid >> 6;
    int inner = tid & 63;
    int bg = inner >> 3, b0 = bg * 8;
    int jl = inner & 7;
    int j0 = blockIdx.x * 8;
    int j = j0 + jl;

    unsigned long long ar[4] = {0ull,0ull,0ull,0ull};
    unsigned long long az[4] = {0ull,0ull,0ull,0ull};
    unsigned long long an[4] = {0ull,0ull,0ull,0ull};

    for (int kc = 0; kc < HID; kc += 64) {
#pragma unroll
        for (int q = 0; q < 4; q++) {
            int id = tid + q * 256;   // 0..1023 float4 ids
            int b = id >> 4;
            int kq = (id & 15) * 4;
            float4 v = *(const float4*)(h_in + b * HID + kc + kq);
            hT[kq + 0][b] = v.x; hT[kq + 1][b] = v.y;
            hT[kq + 2][b] = v.z; hT[kq + 3][b] = v.w;
        }
#pragma unroll
        for (int q = 0; q < 6; q++) {
            int id = tid + q * 256;   // 0..1535
            int k = id / 24, c = id - k * 24;
            int gate = c >> 3, jj = c & 7;
            ws[k][c] = g_whhT[(kc + k) * G3 + gate * HID + j0 + jj];
        }
        __syncthreads();
        int kbase = kg * 16;
#pragma unroll
        for (int i = 0; i < 16; i++) {
            int k = kbase + i;
            unsigned long long wr = pack2(ws[k][jl]);
            unsigned long long wz = pack2(ws[k][8 + jl]);
            unsigned long long wn = pack2(ws[k][16 + jl]);
#pragma unroll
            for (int p = 0; p < 4; p++) {
                unsigned long long hp =
                    *(const unsigned long long*)&hT[k][b0 + 2 * p];
                fma2(ar[p], wr, hp);
                fma2(az[p], wz, hp);
                fma2(an[p], wn, hp);
            }
        }
        __syncthreads();
    }
    float* rp = &red[kg][inner][0];
#pragma unroll
    for (int p = 0; p < 4; p++) {
        float lo, hi;
        unpack2(ar[p], lo, hi); rp[2*p] = lo;      rp[2*p+1] = hi;
        unpack2(az[p], lo, hi); rp[8+2*p] = lo;    rp[8+2*p+1] = hi;
        unpack2(an[p], lo, hi); rp[16+2*p] = lo;   rp[16+2*p+1] = hi;
    }
    __syncthreads();
    if (kg == 0) {
        for (int bi = 0; bi < 8; bi++) {
            int b = b0 + bi;
            float sr = 0.f, sz = 0.f, sn = 0.f;
#pragma unroll
            for (int g = 0; g < 4; g++) {
                sr += red[g][inner][bi];
                sz += red[g][inner][8 + bi];
                sn += red[g][inner][16 + bi];
            }
            sr += b_hh[j]; sz += b_hh[HID + j]; sn += b_hh[2 * HID + j];
            const float* xrow = g_xg + ((long)b * NSTEP + t) * G3;
            float r = 1.f / (1.f + expf(-(xrow[j] + sr)));
            float z = 1.f / (1.f + expf(-(xrow[HID + j] + sz)));
            float n = tanhf(xrow[2 * HID + j] + r * sn);
            float hp = h_in[b * HID + j];
            float hn = (1.f - z) * n + z * hp;
            h_out[b * HID + j] = hn;
            hs[((long)b * NSTEP + t) * HID + j] = hn;
        }
    }
}

// ---------------- launch ----------------
extern "C" void kernel_launch(void* const* d_in, const int* in_sizes, int n_in,
                              void* d_out, int out_size) {
    const float* word_embs = (const float*)d_in[0];
    const float* vis       = (const float*)d_in[1];
    const float* tof       = (const float*)d_in[2];
    // d_in[3] = lang_len (int64) unused by reference computation
    const float* W_map     = (const float*)d_in[4];
    const float* b_map     = (const float*)d_in[5];
    const float* w_ih      = (const float*)d_in[6];
    const float* w_hh      = (const float*)d_in[7];
    const float* b_ih      = (const float*)d_in[8];
    const float* b_hh      = (const float*)d_in[9];
    const float* W_cls     = (const float*)d_in[10];
    const float* b_cls     = (const float*)d_in[11];
    float* out = (float*)d_out;

    float *wihT, *whhT, *xg, *h, *hs;
    cudaGetSymbolAddress((void**)&wihT, g_wihT);
    cudaGetSymbolAddress((void**)&whhT, g_whhT);
    cudaGetSymbolAddress((void**)&xg,   g_xg);
    cudaGetSymbolAddress((void**)&h,    g_h);
    cudaGetSymbolAddress((void**)&hs,   g_hs);

    // 1) transpose GRU weights to K-major
    {
        int total = EMB * G3 + HID * G3;
        transpose_weights<<<(total + 255) / 256, 256>>>(w_ih, w_hh);
    }
    // 2) h0
    h0_kernel<<<64, 256>>>(vis, tof, W_map, b_map, h /* g_h[0] */);
    // 3) x_gates = word_embs[:, :31] @ w_ih^T + b_ih  -> g_xg[m][1536]
    {
        dim3 grid(G3 / 128, (MROWS + 127) / 128);
        gemm128<<<grid, 256>>>(word_embs, wihT, b_ih, xg,
                               MROWS, G3, EMB, /*a_mode=*/1);
    }
    // 4) 31 sequential GRU steps (ping-pong hidden state)
    for (int t = 0; t < NSTEP; t++) {
        const float* hin = h + (t & 1) * (B_SZ * HID);
        float* hout      = h + ((t + 1) & 1) * (B_SZ * HID);
        gru_step<<<64, 256>>>(hin, hout, hs, b_hh, t);
    }
    // 5) classifier: logits = hs @ W_cls + b_cls -> d_out [1984, 32000]
    {
        dim3 grid(VOCAB / 128, (MROWS + 127) / 128);
        gemm128<<<grid, 256>>>(hs, W_cls, b_cls, out,
                               MROWS, VOCAB, HID, /*a_mode=*/0);
    }
    (void)in_sizes; (void)n_in; (void)out_size;
}

// round 5
// speedup vs baseline: 2.6730x; 1.7968x over previous
#include <cuda_runtime.h>
#include <cuda_bf16.h>
#include <math.h>
#include <stdint.h>

typedef unsigned long long ull;

#define B_SZ   64
#define NSTEP  31
#define EMB    300
#define FEAT   4100
#define HID    512
#define G3     1536
#define VOCAB  32000
#define MROWS  1984
#define MPAD   2048

// ---------------- device scratch ----------------
__device__ float g_wihT[EMB * G3];
__device__ float g_xg[MROWS * G3];
__device__ float g_ht[2][HID * B_SZ];     // transposed hidden [j][b]
__device__ float g_hs[MROWS * HID];
__device__ __nv_bfloat16 g_Ah[MPAD * HID];
__device__ __nv_bfloat16 g_Al[MPAD * HID];
__device__ __nv_bfloat16 g_Bh[(long)VOCAB * HID];
__device__ __nv_bfloat16 g_Bl[(long)VOCAB * HID];

// ---------------- f32x2 helpers ----------------
__device__ __forceinline__ void fma2(ull& d, ull a, ull b) {
    asm("fma.rn.f32x2 %0, %1, %2, %0;" : "+l"(d) : "l"(a), "l"(b));
}
__device__ __forceinline__ ull pack2(float x) {
    ull r; asm("mov.b64 %0, {%1, %2};" : "=l"(r) : "f"(x), "f"(x)); return r;
}
__device__ __forceinline__ void unpack2(ull d, float& lo, float& hi) {
    asm("mov.b64 {%0, %1}, %2;" : "=f"(lo), "=f"(hi) : "l"(d));
}
__device__ __forceinline__ uint32_t s2u(const void* p) {
    uint32_t a;
    asm("{ .reg .u64 t; cvta.to.shared.u64 t, %1; cvt.u32.u64 %0, t; }"
        : "=r"(a) : "l"(p));
    return a;
}
__device__ __forceinline__ uint32_t swz(uint32_t bo) {
    return bo ^ ((bo >> 3) & 0x70);
}

// ---------------- small prep kernels ----------------
__global__ void transpose_wih(const float* __restrict__ w_ih) {
    int idx = blockIdx.x * 256 + threadIdx.x;
    if (idx < EMB * G3) {
        int k = idx / G3, g = idx - k * G3;
        g_wihT[idx] = w_ih[g * EMB + k];
    }
}

__global__ void convert_A(const float* __restrict__ hs) {
    int idx = blockIdx.x * 256 + threadIdx.x;
    float4 v = make_float4(0.f, 0.f, 0.f, 0.f);
    if (idx < (MROWS * HID) / 4) v = *(const float4*)(hs + (long)idx * 4);
    float a[4] = {v.x, v.y, v.z, v.w};
#pragma unroll
    for (int i = 0; i < 4; i++) {
        __nv_bfloat16 h = __float2bfloat16_rn(a[i]);
        g_Ah[(long)idx * 4 + i] = h;
        g_Al[(long)idx * 4 + i] = __float2bfloat16_rn(a[i] - __bfloat162float(h));
    }
}

// W_cls [512][32000] -> Bh/Bl [32000][512]
__global__ void convert_W(const float* __restrict__ W) {
    __shared__ float tile[32][33];
    int n0 = blockIdx.x * 32, k0 = blockIdx.y * 32;
    int tx = threadIdx.x, ty = threadIdx.y;
#pragma unroll
    for (int j = 0; j < 32; j += 8)
        tile[ty + j][tx] = W[(long)(k0 + ty + j) * VOCAB + n0 + tx];
    __syncthreads();
#pragma unroll
    for (int j = 0; j < 32; j += 8) {
        int n = n0 + ty + j, k = k0 + tx;
        float v = tile[tx][ty + j];
        __nv_bfloat16 h = __float2bfloat16_rn(v);
        g_Bh[(long)n * HID + k] = h;
        g_Bl[(long)n * HID + k] = __float2bfloat16_rn(v - __bfloat162float(h));
    }
}

// ---------------- fp32 tiled GEMM (x_gates only) ----------------
__global__ __launch_bounds__(256)
void gemm128(const float* __restrict__ A, const float* __restrict__ Bm,
             const float* __restrict__ bias, float* __restrict__ C,
             int M, int N, int K) {
    __shared__ __align__(16) float As[16][132];
    __shared__ __align__(16) float Bs[16][128];
    int tid = threadIdx.x;
    int mtile = blockIdx.y * 128;
    int ntile = blockIdx.x * 128;
    int tm = tid >> 4, tn = tid & 15;
    int m0 = tm * 8, n0 = tn * 8;

    ull acc[8][4];
#pragma unroll
    for (int i = 0; i < 8; i++)
#pragma unroll
        for (int j = 0; j < 4; j++) acc[i][j] = 0ull;

    int nchunks = (K + 15) >> 4;
    for (int c = 0; c < nchunks; c++) {
        int kc = c << 4;
#pragma unroll
        for (int q = 0; q < 2; q++) {
            int id = tid * 2 + q;
            int row = id >> 2;
            int kq = (id & 3) * 4;
            int m = mtile + row;
            float4 v = make_float4(0.f, 0.f, 0.f, 0.f);
            if (m < M) {
                int bb = m / 31, tt = m - bb * 31;
                long roff = (long)(bb * 32 + tt) * K;
                int k = kc + kq;
                if (k + 3 < K) v = *(const float4*)(A + roff + k);
                else {
                    float tmp[4] = {0.f, 0.f, 0.f, 0.f};
#pragma unroll
                    for (int u = 0; u < 4; u++)
                        if (k + u < K) tmp[u] = A[roff + k + u];
                    v = make_float4(tmp[0], tmp[1], tmp[2], tmp[3]);
                }
            }
            As[kq + 0][row] = v.x; As[kq + 1][row] = v.y;
            As[kq + 2][row] = v.z; As[kq + 3][row] = v.w;
        }
#pragma unroll
        for (int q = 0; q < 2; q++) {
            int id = tid + q * 256;
            int r = id >> 5;
            int nq = (id & 31) * 4;
            int k = kc + r;
            float4 v = make_float4(0.f, 0.f, 0.f, 0.f);
            if (k < K) v = *(const float4*)(Bm + (long)k * N + ntile + nq);
            *(float4*)&Bs[r][nq] = v;
        }
        __syncthreads();
#pragma unroll
        for (int kk = 0; kk < 16; kk++) {
            float4 a0 = *(const float4*)&As[kk][m0];
            float4 a1 = *(const float4*)&As[kk][m0 + 4];
            const ull* bp = (const ull*)&Bs[kk][n0];
            ull b2[4] = {bp[0], bp[1], bp[2], bp[3]};
            float av[8] = {a0.x, a0.y, a0.z, a0.w, a1.x, a1.y, a1.z, a1.w};
#pragma unroll
            for (int i = 0; i < 8; i++) {
                ull ai = pack2(av[i]);
#pragma unroll
                for (int j = 0; j < 4; j++) fma2(acc[i][j], ai, b2[j]);
            }
        }
        __syncthreads();
    }
    float bvals[8];
#pragma unroll
    for (int j = 0; j < 8; j++) bvals[j] = bias[ntile + n0 + j];
#pragma unroll
    for (int i = 0; i < 8; i++) {
        int m = mtile + m0 + i;
        if (m < M) {
            float* crow = C + (long)m * N + ntile + n0;
#pragma unroll
            for (int j = 0; j < 4; j++) {
                float lo, hi; unpack2(acc[i][j], lo, hi);
                crow[2 * j]     = lo + bvals[2 * j];
                crow[2 * j + 1] = hi + bvals[2 * j + 1];
            }
        }
    }
}

// ---------------- h0 (writes transposed h[j][b]) ----------------
__global__ __launch_bounds__(256)
void h0_kernel(const float* __restrict__ vis, const float* __restrict__ tof,
               const float* __restrict__ W_map, const float* __restrict__ b_map,
               float* __restrict__ h_out) {
    __shared__ __align__(16) float fT[64][66];
    __shared__ float ws[64][8];
    __shared__ float red[4][64][8];
    int tid = threadIdx.x;
    int kg = tid >> 6;
    int inner = tid & 63;
    int bg = inner >> 3, b0 = bg * 8;
    int jl = inner & 7;
    int j0 = blockIdx.x * 8;
    int j = j0 + jl;

    ull acc[4] = {0ull, 0ull, 0ull, 0ull};

    for (int kc = 0; kc < FEAT; kc += 64) {
#pragma unroll
        for (int q = 0; q < 16; q++) {
            int id = tid + q * 256;
            int b = id >> 6, kq = id & 63;
            int f = kc + kq;
            float v = 0.f;
            if (f < 2048) v = vis[b * 2048 + f];
            else if (f < FEAT) v = tof[b * 2052 + (f - 2048)];
            fT[kq][b] = v;
        }
#pragma unroll
        for (int q = 0; q < 2; q++) {
            int id = tid + q * 256;
            int k = id >> 3, jj = id & 7;
            int f = kc + k;
            ws[k][jj] = (f < FEAT) ? W_map[f * HID + j0 + jj] : 0.f;
        }
        __syncthreads();
        int kbase = kg * 16;
#pragma unroll
        for (int i = 0; i < 16; i++) {
            int k = kbase + i;
            ull w2 = pack2(ws[k][jl]);
#pragma unroll
            for (int p = 0; p < 4; p++) {
                ull hp = *(const ull*)&fT[k][b0 + 2 * p];
                fma2(acc[p], w2, hp);
            }
        }
        __syncthreads();
    }
#pragma unroll
    for (int p = 0; p < 4; p++) {
        float lo, hi; unpack2(acc[p], lo, hi);
        red[kg][inner][2 * p] = lo; red[kg][inner][2 * p + 1] = hi;
    }
    __syncthreads();
    if (kg == 0) {
        for (int bi = 0; bi < 8; bi++) {
            int b = b0 + bi;
            float s = 0.f;
#pragma unroll
            for (int g = 0; g < 4; g++) s += red[g][inner][bi];
            s += b_map[j];
            h_out[j * B_SZ + b] = fmaxf(s, 0.f);   // transposed store
        }
    }
}

// ---------------- GRU step: 128 blocks, block owns 4 hidden cols ----------
// smem: h_t[512][68] + w_t[512][16] + part[16][16][48]
#define HTP 68
#define WTP 16
#define GRU_SMEM ((HID * HTP + HID * WTP + 16 * 16 * 48) * 4)

__global__ void __launch_bounds__(256)
gru_step3(const float* __restrict__ h_in, float* __restrict__ h_out,
          float* __restrict__ hs, const float* __restrict__ w_hh,
          const float* __restrict__ b_hh, int t) {
    extern __shared__ float sm[];
    float* h_t = sm;                       // [512][68]  (h[b][k] at h_t[k*68+b])
    float* w_t = h_t + HID * HTP;          // [512][16]  pos0-5 = gc0-5, pos8-13 = gc6-11
    float* part = w_t + HID * WTP;         // [16 ks][16 tile][48]
    int tid = threadIdx.x;
    int j0 = blockIdx.x * 4;

    // load h (transposed global [j][b] -> h_t[k][b])
#pragma unroll
    for (int q = 0; q < 8; q++) {
        int id = tid + q * 256;            // 8192 float4
        int k = id >> 2, b4 = (id & 3) * 16;
        float4 v0 = *(const float4*)(h_in + k * B_SZ + b4);
        float4 v1 = *(const float4*)(h_in + k * B_SZ + b4 + 4);
        float4 v2 = *(const float4*)(h_in + k * B_SZ + b4 + 8);
        float4 v3 = *(const float4*)(h_in + k * B_SZ + b4 + 12);
        *(float4*)(h_t + k * HTP + b4)      = v0;
        *(float4*)(h_t + k * HTP + b4 + 4)  = v1;
        *(float4*)(h_t + k * HTP + b4 + 8)  = v2;
        *(float4*)(h_t + k * HTP + b4 + 12) = v3;
    }
    // load w rows (12 x 512) -> w_t[k][pos]
#pragma unroll
    for (int q = 0; q < 6; q++) {
        int id = tid + q * 256;            // 1536 float4
        int r = id % 12, k4 = id / 12;
        int grow = (r >> 2) * HID + j0 + (r & 3);
        int pos = (r < 6) ? r : r + 2;
        float4 v = *(const float4*)(w_hh + (long)grow * HID + k4 * 4);
        w_t[(k4 * 4 + 0) * WTP + pos] = v.x;
        w_t[(k4 * 4 + 1) * WTP + pos] = v.y;
        w_t[(k4 * 4 + 2) * WTP + pos] = v.z;
        w_t[(k4 * 4 + 3) * WTP + pos] = v.w;
    }
    __syncthreads();

    // GEMM: 16 k-slices x 16 tiles (8 bgroups x 2 gcgroups), thread = 8b x 6gc
    int ks = tid >> 4;
    int tile = tid & 15;
    int bg = tile >> 1, gcg = tile & 1;
    int b0 = bg * 8, gbase = gcg * 8;
    ull acc[4][6];
#pragma unroll
    for (int p = 0; p < 4; p++)
#pragma unroll
        for (int g = 0; g < 6; g++) acc[p][g] = 0ull;

    int kbase = ks * 32;
#pragma unroll 4
    for (int kk = 0; kk < 32; kk++) {
        int k = kbase + kk;
        const float* hr = h_t + k * HTP + b0;
        ulonglong2 ha = *(const ulonglong2*)(hr);
        ulonglong2 hb = *(const ulonglong2*)(hr + 4);
        ull h2[4] = {ha.x, ha.y, hb.x, hb.y};
        float4 w0 = *(const float4*)(w_t + k * WTP + gbase);
        float4 w1 = *(const float4*)(w_t + k * WTP + gbase + 4);
        float wv[6] = {w0.x, w0.y, w0.z, w0.w, w1.x, w1.y};
#pragma unroll
        for (int g = 0; g < 6; g++) {
            ull wp = pack2(wv[g]);
#pragma unroll
            for (int p = 0; p < 4; p++) fma2(acc[p][g], wp, h2[p]);
        }
    }
    // store partials
    float* pb = part + (ks * 16 + tile) * 48;
#pragma unroll
    for (int g = 0; g < 6; g++) {
        float l0, h0v, l1, h1, l2, h2v, l3, h3;
        unpack2(acc[0][g], l0, h0v); unpack2(acc[1][g], l1, h1);
        unpack2(acc[2][g], l2, h2v); unpack2(acc[3][g], l3, h3);
        *(float4*)(pb + g * 8)     = make_float4(l0, h0v, l1, h1);
        *(float4*)(pb + g * 8 + 4) = make_float4(l2, h2v, l3, h3);
    }
    __syncthreads();

    // reduce + nonlinearity: thread = (b, jg)
    int b = tid & 63, jg = tid >> 6;
    int bgr = b >> 3, bi = b & 7;
    int tR = bgr * 2 + 0, iR = jg * 8 + bi;                       // gc=jg (grp0)
    int tZ, iZ;
    if (jg < 2) { tZ = bgr * 2 + 0; iZ = (4 + jg) * 8 + bi; }     // gc=4+jg
    else        { tZ = bgr * 2 + 1; iZ = (jg - 2) * 8 + bi; }     // gc-6
    int tN = bgr * 2 + 1, iN = (2 + jg) * 8 + bi;                 // gc=8+jg -> grp1 idx 2+jg
    float sr = 0.f, sz = 0.f, sn = 0.f;
#pragma unroll
    for (int s = 0; s < 16; s++) {
        sr += part[(s * 16 + tR) * 48 + iR];
        sz += part[(s * 16 + tZ) * 48 + iZ];
        sn += part[(s * 16 + tN) * 48 + iN];
    }
    int j = j0 + jg;
    sr += b_hh[j]; sz += b_hh[HID + j]; sn += b_hh[2 * HID + j];
    const float* xrow = g_xg + ((long)b * NSTEP + t) * G3;
    float r_ = 1.f / (1.f + expf(-(xrow[j] + sr)));
    float z_ = 1.f / (1.f + expf(-(xrow[HID + j] + sz)));
    float n_ = tanhf(xrow[2 * HID + j] + r_ * sn);
    float hp = h_t[j * HTP + b];
    float hn = (1.f - z_) * n_ + z_ * hp;
    h_out[j * B_SZ + b] = hn;
    hs[((long)b * NSTEP + t) * HID + j] = hn;
}

// ---------------- classifier: mma.sync bf16 3-split GEMM -----------------
// CTA 128x128, 8 warps (2Mx4N), warp 64x32, K chunks of 64, smem swizzled.
#define CLS_SMEM 65536
#define OA_H 0
#define OA_L 16384
#define OB_H 32768
#define OB_L 49152

__global__ void __launch_bounds__(256)
cls_mma2(const float* __restrict__ bias, float* __restrict__ out) {
    extern __shared__ char csm[];
    uint32_t sb = s2u(csm);
    int tid = threadIdx.x;
    int wid = tid >> 5, l = tid & 31;
    int wm = wid >> 2, wn = wid & 3;          // warp coords
    int mtile = blockIdx.y * 128;
    int ntile = blockIdx.x * 128;

    float d[4][4][4];
#pragma unroll
    for (int i = 0; i < 4; i++)
#pragma unroll
        for (int j = 0; j < 4; j++)
#pragma unroll
            for (int k = 0; k < 4; k++) d[i][j][k] = 0.f;

    // per-lane ldmatrix source coords
    int rA = l & 15, kA = (l >> 4) * 8;               // A x4
    int rB = l & 7,  kB = ((l >> 3) & 1) * 8;         // B x2 (lanes 0-15)

    for (int c = 0; c < 8; c++) {
        int kc = c * 64;
        __syncthreads();
        // fill smem: 4096 uint4
#pragma unroll
        for (int q = 0; q < 16; q++) {
            int id = tid + q * 256;
            int seg = id >> 10;
            int r = (id >> 3) & 127;
            int c16 = id & 7;
            const __nv_bfloat16* src;
            if (seg == 0)      src = g_Ah + (long)(mtile + r) * HID;
            else if (seg == 1) src = g_Al + (long)(mtile + r) * HID;
            else if (seg == 2) src = g_Bh + (long)(ntile + r) * HID;
            else               src = g_Bl + (long)(ntile + r) * HID;
            uint4 v = *(const uint4*)(src + kc + c16 * 8);
            *(uint4*)(csm + seg * 16384 + swz((uint32_t)(r * 128 + c16 * 16))) = v;
        }
        __syncthreads();

#pragma unroll
        for (int s = 0; s < 3; s++) {
            uint32_t aoff = (s == 2) ? OA_L : OA_H;
            uint32_t boff = (s == 1) ? OB_L : OB_H;
#pragma unroll
            for (int kst = 0; kst < 4; kst++) {
                // load B frags: 4 n-tiles
                uint32_t bf[4][2];
#pragma unroll
                for (int nt = 0; nt < 4; nt++) {
                    int row = wn * 32 + nt * 8 + rB;
                    uint32_t addr = sb + boff +
                        swz((uint32_t)(row * 128 + (kst * 16 + kB) * 2));
                    asm volatile(
                        "ldmatrix.sync.aligned.m8n8.x2.shared.b16 {%0,%1}, [%2];"
                        : "=r"(bf[nt][0]), "=r"(bf[nt][1]) : "r"(addr));
                }
#pragma unroll
                for (int mt = 0; mt < 4; mt++) {
                    int row = wm * 64 + mt * 16 + rA;
                    uint32_t addr = sb + aoff +
                        swz((uint32_t)(row * 128 + (kst * 16 + kA) * 2));
                    uint32_t a0, a1, a2, a3;
                    asm volatile(
                        "ldmatrix.sync.aligned.m8n8.x4.shared.b16 {%0,%1,%2,%3}, [%4];"
                        : "=r"(a0), "=r"(a1), "=r"(a2), "=r"(a3) : "r"(addr));
#pragma unroll
                    for (int nt = 0; nt < 4; nt++) {
                        asm volatile(
                            "mma.sync.aligned.m16n8k16.row.col.f32.bf16.bf16.f32 "
                            "{%0,%1,%2,%3}, {%4,%5,%6,%7}, {%8,%9}, {%0,%1,%2,%3};"
                            : "+f"(d[mt][nt][0]), "+f"(d[mt][nt][1]),
                              "+f"(d[mt][nt][2]), "+f"(d[mt][nt][3])
                            : "r"(a0), "r"(a1), "r"(a2), "r"(a3),
                              "r"(bf[nt][0]), "r"(bf[nt][1]));
                    }
                }
            }
        }
    }

    // epilogue
    int rbase = mtile + wm * 64 + (l >> 2);
    int cbase = ntile + wn * 32 + (l & 3) * 2;
#pragma unroll
    for (int nt = 0; nt < 4; nt++) {
        int col = cbase + nt * 8;
        float b0 = bias[col], b1 = bias[col + 1];
#pragma unroll
        for (int mt = 0; mt < 4; mt++) {
            int r0 = rbase + mt * 16;
            if (r0 < MROWS) {
                float2 v = make_float2(d[mt][nt][0] + b0, d[mt][nt][1] + b1);
                *(float2*)(out + (long)r0 * VOCAB + col) = v;
            }
            if (r0 + 8 < MROWS) {
                float2 v = make_float2(d[mt][nt][2] + b0, d[mt][nt][3] + b1);
                *(float2*)(out + (long)(r0 + 8) * VOCAB + col) = v;
            }
        }
    }
}

// ---------------- launch ----------------
extern "C" void kernel_launch(void* const* d_in, const int* in_sizes, int n_in,
                              void* d_out, int out_size) {
    const float* word_embs = (const float*)d_in[0];
    const float* vis       = (const float*)d_in[1];
    const float* tof       = (const float*)d_in[2];
    const float* W_map     = (const float*)d_in[4];
    const float* b_map     = (const float*)d_in[5];
    const float* w_ih      = (const float*)d_in[6];
    const float* w_hh      = (const float*)d_in[7];
    const float* b_ih      = (const float*)d_in[8];
    const float* b_hh      = (const float*)d_in[9];
    const float* W_cls     = (const float*)d_in[10];
    const float* b_cls     = (const float*)d_in[11];
    float* out = (float*)d_out;

    float *wihT, *xg, *ht, *hs;
    cudaGetSymbolAddress((void**)&wihT, g_wihT);
    cudaGetSymbolAddress((void**)&xg,   g_xg);
    cudaGetSymbolAddress((void**)&ht,   g_ht);
    cudaGetSymbolAddress((void**)&hs,   g_hs);

    cudaFuncSetAttribute(gru_step3, cudaFuncAttributeMaxDynamicSharedMemorySize,
                         GRU_SMEM);
    cudaFuncSetAttribute(cls_mma2, cudaFuncAttributeMaxDynamicSharedMemorySize,
                         CLS_SMEM);

    transpose_wih<<<(EMB * G3 + 255) / 256, 256>>>(w_ih);
    h0_kernel<<<64, 256>>>(vis, tof, W_map, b_map, ht);
    {
        dim3 grid(G3 / 128, (MROWS + 127) / 128);
        gemm128<<<grid, 256>>>(word_embs, wihT, b_ih, xg, MROWS, G3, EMB);
    }
    {
        dim3 grid(VOCAB / 32, HID / 32);
        convert_W<<<grid, dim3(32, 8)>>>(W_cls);
    }
    for (int t = 0; t < NSTEP; t++) {
        const float* hin = ht + (t & 1) * (HID * B_SZ);
        float* hout      = ht + ((t + 1) & 1) * (HID * B_SZ);
        gru_step3<<<128, 256, GRU_SMEM>>>(hin, hout, hs, w_hh, b_hh, t);
    }
    convert_A<<<(MPAD * HID / 4) / 256, 256>>>(hs);
    {
        dim3 grid(VOCAB / 128, MPAD / 128);
        cls_mma2<<<grid, 256, CLS_SMEM>>>(b_cls, out);
    }
    (void)in_sizes; (void)n_in; (void)out_size;
}

// round 6
// speedup vs baseline: 2.9670x; 1.1100x over previous
#include <cuda_runtime.h>
#include <cuda_bf16.h>
#include <math.h>
#include <stdint.h>

typedef unsigned long long ull;

#define B_SZ   64
#define NSTEP  31
#define EMB    300
#define FEAT   4100
#define HID    512
#define G3     1536
#define VOCAB  32000
#define MROWS  1984
#define MPAD   2048

// ---------------- device scratch ----------------
__device__ float g_wihT[EMB * G3];
__device__ float g_xg[MROWS * G3];
__device__ float g_ht[2][HID * B_SZ];     // transposed hidden [j][b]
__device__ float g_hs[MROWS * HID];
__device__ __nv_bfloat16 g_Ah[MPAD * HID];
__device__ __nv_bfloat16 g_Al[MPAD * HID];
__device__ __nv_bfloat16 g_Bh[(long)VOCAB * HID];
__device__ __nv_bfloat16 g_Bl[(long)VOCAB * HID];

// ---------------- f32x2 helpers ----------------
__device__ __forceinline__ void fma2(ull& d, ull a, ull b) {
    asm("fma.rn.f32x2 %0, %1, %2, %0;" : "+l"(d) : "l"(a), "l"(b));
}
__device__ __forceinline__ ull pack2(float x) {
    ull r; asm("mov.b64 %0, {%1, %2};" : "=l"(r) : "f"(x), "f"(x)); return r;
}
__device__ __forceinline__ void unpack2(ull d, float& lo, float& hi) {
    asm("mov.b64 {%0, %1}, %2;" : "=f"(lo), "=f"(hi) : "l"(d));
}
__device__ __forceinline__ uint32_t s2u(const void* p) {
    uint32_t a;
    asm("{ .reg .u64 t; cvta.to.shared.u64 t, %1; cvt.u32.u64 %0, t; }"
        : "=r"(a) : "l"(p));
    return a;
}
__device__ __forceinline__ uint32_t swz(uint32_t bo) {
    return bo ^ ((bo >> 3) & 0x70);
}

// ---------------- small prep kernels ----------------
__global__ void transpose_wih(const float* __restrict__ w_ih) {
    int idx = blockIdx.x * 256 + threadIdx.x;
    if (idx < EMB * G3) {
        int k = idx / G3, g = idx - k * G3;
        g_wihT[idx] = w_ih[g * EMB + k];
    }
}

__global__ void convert_A(const float* __restrict__ hs) {
    int idx = blockIdx.x * 256 + threadIdx.x;
    float4 v = make_float4(0.f, 0.f, 0.f, 0.f);
    if (idx < (MROWS * HID) / 4) v = *(const float4*)(hs + (long)idx * 4);
    float a[4] = {v.x, v.y, v.z, v.w};
#pragma unroll
    for (int i = 0; i < 4; i++) {
        __nv_bfloat16 h = __float2bfloat16_rn(a[i]);
        g_Ah[(long)idx * 4 + i] = h;
        g_Al[(long)idx * 4 + i] = __float2bfloat16_rn(a[i] - __bfloat162float(h));
    }
}

// W_cls [512][32000] -> Bh/Bl [32000][512]
__global__ void convert_W(const float* __restrict__ W) {
    __shared__ float tile[32][33];
    int n0 = blockIdx.x * 32, k0 = blockIdx.y * 32;
    int tx = threadIdx.x, ty = threadIdx.y;
#pragma unroll
    for (int j = 0; j < 32; j += 8)
        tile[ty + j][tx] = W[(long)(k0 + ty + j) * VOCAB + n0 + tx];
    __syncthreads();
#pragma unroll
    for (int j = 0; j < 32; j += 8) {
        int n = n0 + ty + j, k = k0 + tx;
        float v = tile[tx][ty + j];
        __nv_bfloat16 h = __float2bfloat16_rn(v);
        g_Bh[(long)n * HID + k] = h;
        g_Bl[(long)n * HID + k] = __float2bfloat16_rn(v - __bfloat162float(h));
    }
}

// ---------------- fp32 tiled GEMM (x_gates only) ----------------
__global__ __launch_bounds__(256)
void gemm128(const float* __restrict__ A, const float* __restrict__ Bm,
             const float* __restrict__ bias, float* __restrict__ C,
             int M, int N, int K) {
    __shared__ __align__(16) float As[16][132];
    __shared__ __align__(16) float Bs[16][128];
    int tid = threadIdx.x;
    int mtile = blockIdx.y * 128;
    int ntile = blockIdx.x * 128;
    int tm = tid >> 4, tn = tid & 15;
    int m0 = tm * 8, n0 = tn * 8;

    ull acc[8][4];
#pragma unroll
    for (int i = 0; i < 8; i++)
#pragma unroll
        for (int j = 0; j < 4; j++) acc[i][j] = 0ull;

    int nchunks = (K + 15) >> 4;
    for (int c = 0; c < nchunks; c++) {
        int kc = c << 4;
#pragma unroll
        for (int q = 0; q < 2; q++) {
            int id = tid * 2 + q;
            int row = id >> 2;
            int kq = (id & 3) * 4;
            int m = mtile + row;
            float4 v = make_float4(0.f, 0.f, 0.f, 0.f);
            if (m < M) {
                int bb = m / 31, tt = m - bb * 31;
                long roff = (long)(bb * 32 + tt) * K;
                int k = kc + kq;
                if (k + 3 < K) v = *(const float4*)(A + roff + k);
                else {
                    float tmp[4] = {0.f, 0.f, 0.f, 0.f};
#pragma unroll
                    for (int u = 0; u < 4; u++)
                        if (k + u < K) tmp[u] = A[roff + k + u];
                    v = make_float4(tmp[0], tmp[1], tmp[2], tmp[3]);
                }
            }
            As[kq + 0][row] = v.x; As[kq + 1][row] = v.y;
            As[kq + 2][row] = v.z; As[kq + 3][row] = v.w;
        }
#pragma unroll
        for (int q = 0; q < 2; q++) {
            int id = tid + q * 256;
            int r = id >> 5;
            int nq = (id & 31) * 4;
            int k = kc + r;
            float4 v = make_float4(0.f, 0.f, 0.f, 0.f);
            if (k < K) v = *(const float4*)(Bm + (long)k * N + ntile + nq);
            *(float4*)&Bs[r][nq] = v;
        }
        __syncthreads();
#pragma unroll
        for (int kk = 0; kk < 16; kk++) {
            float4 a0 = *(const float4*)&As[kk][m0];
            float4 a1 = *(const float4*)&As[kk][m0 + 4];
            const ull* bp = (const ull*)&Bs[kk][n0];
            ull b2[4] = {bp[0], bp[1], bp[2], bp[3]};
            float av[8] = {a0.x, a0.y, a0.z, a0.w, a1.x, a1.y, a1.z, a1.w};
#pragma unroll
            for (int i = 0; i < 8; i++) {
                ull ai = pack2(av[i]);
#pragma unroll
                for (int j = 0; j < 4; j++) fma2(acc[i][j], ai, b2[j]);
            }
        }
        __syncthreads();
    }
    float bvals[8];
#pragma unroll
    for (int j = 0; j < 8; j++) bvals[j] = bias[ntile + n0 + j];
#pragma unroll
    for (int i = 0; i < 8; i++) {
        int m = mtile + m0 + i;
        if (m < M) {
            float* crow = C + (long)m * N + ntile + n0;
#pragma unroll
            for (int j = 0; j < 4; j++) {
                float lo, hi; unpack2(acc[i][j], lo, hi);
                crow[2 * j]     = lo + bvals[2 * j];
                crow[2 * j + 1] = hi + bvals[2 * j + 1];
            }
        }
    }
}

// ---------------- h0 (writes transposed h[j][b]) ----------------
__global__ __launch_bounds__(256)
void h0_kernel(const float* __restrict__ vis, const float* __restrict__ tof,
               const float* __restrict__ W_map, const float* __restrict__ b_map,
               float* __restrict__ h_out) {
    __shared__ __align__(16) float fT[64][66];
    __shared__ float ws[64][8];
    __shared__ float red[4][64][8];
    int tid = threadIdx.x;
    int kg = tid >> 6;
    int inner = tid & 63;
    int bg = inner >> 3, b0 = bg * 8;
    int jl = inner & 7;
    int j0 = blockIdx.x * 8;
    int j = j0 + jl;

    ull acc[4] = {0ull, 0ull, 0ull, 0ull};

    for (int kc = 0; kc < FEAT; kc += 64) {
#pragma unroll
        for (int q = 0; q < 16; q++) {
            int id = tid + q * 256;
            int b = id >> 6, kq = id & 63;
            int f = kc + kq;
            float v = 0.f;
            if (f < 2048) v = vis[b * 2048 + f];
            else if (f < FEAT) v = tof[b * 2052 + (f - 2048)];
            fT[kq][b] = v;
        }
#pragma unroll
        for (int q = 0; q < 2; q++) {
            int id = tid + q * 256;
            int k = id >> 3, jj = id & 7;
            int f = kc + k;
            ws[k][jj] = (f < FEAT) ? W_map[f * HID + j0 + jj] : 0.f;
        }
        __syncthreads();
        int kbase = kg * 16;
#pragma unroll
        for (int i = 0; i < 16; i++) {
            int k = kbase + i;
            ull w2 = pack2(ws[k][jl]);
#pragma unroll
            for (int p = 0; p < 4; p++) {
                ull hp = *(const ull*)&fT[k][b0 + 2 * p];
                fma2(acc[p], w2, hp);
            }
        }
        __syncthreads();
    }
#pragma unroll
    for (int p = 0; p < 4; p++) {
        float lo, hi; unpack2(acc[p], lo, hi);
        red[kg][inner][2 * p] = lo; red[kg][inner][2 * p + 1] = hi;
    }
    __syncthreads();
    if (kg == 0) {
        for (int bi = 0; bi < 8; bi++) {
            int b = b0 + bi;
            float s = 0.f;
#pragma unroll
            for (int g = 0; g < 4; g++) s += red[g][inner][bi];
            s += b_map[j];
            h_out[j * B_SZ + b] = fmaxf(s, 0.f);
        }
    }
}

// ---------------- GRU step (unchanged from round 5) ----------------
#define HTP 68
#define WTP 16
#define GRU_SMEM ((HID * HTP + HID * WTP + 16 * 16 * 48) * 4)

__global__ void __launch_bounds__(256)
gru_step3(const float* __restrict__ h_in, float* __restrict__ h_out,
          float* __restrict__ hs, const float* __restrict__ w_hh,
          const float* __restrict__ b_hh, int t) {
    extern __shared__ float sm[];
    float* h_t = sm;
    float* w_t = h_t + HID * HTP;
    float* part = w_t + HID * WTP;
    int tid = threadIdx.x;
    int j0 = blockIdx.x * 4;

#pragma unroll
    for (int q = 0; q < 8; q++) {
        int id = tid + q * 256;
        int k = id >> 2, b4 = (id & 3) * 16;
        float4 v0 = *(const float4*)(h_in + k * B_SZ + b4);
        float4 v1 = *(const float4*)(h_in + k * B_SZ + b4 + 4);
        float4 v2 = *(const float4*)(h_in + k * B_SZ + b4 + 8);
        float4 v3 = *(const float4*)(h_in + k * B_SZ + b4 + 12);
        *(float4*)(h_t + k * HTP + b4)      = v0;
        *(float4*)(h_t + k * HTP + b4 + 4)  = v1;
        *(float4*)(h_t + k * HTP + b4 + 8)  = v2;
        *(float4*)(h_t + k * HTP + b4 + 12) = v3;
    }
#pragma unroll
    for (int q = 0; q < 6; q++) {
        int id = tid + q * 256;
        int r = id % 12, k4 = id / 12;
        int grow = (r >> 2) * HID + j0 + (r & 3);
        int pos = (r < 6) ? r : r + 2;
        float4 v = *(const float4*)(w_hh + (long)grow * HID + k4 * 4);
        w_t[(k4 * 4 + 0) * WTP + pos] = v.x;
        w_t[(k4 * 4 + 1) * WTP + pos] = v.y;
        w_t[(k4 * 4 + 2) * WTP + pos] = v.z;
        w_t[(k4 * 4 + 3) * WTP + pos] = v.w;
    }
    __syncthreads();

    int ks = tid >> 4;
    int tile = tid & 15;
    int bg = tile >> 1, gcg = tile & 1;
    int b0 = bg * 8, gbase = gcg * 8;
    ull acc[4][6];
#pragma unroll
    for (int p = 0; p < 4; p++)
#pragma unroll
        for (int g = 0; g < 6; g++) acc[p][g] = 0ull;

    int kbase = ks * 32;
#pragma unroll 4
    for (int kk = 0; kk < 32; kk++) {
        int k = kbase + kk;
        const float* hr = h_t + k * HTP + b0;
        ulonglong2 ha = *(const ulonglong2*)(hr);
        ulonglong2 hb = *(const ulonglong2*)(hr + 4);
        ull h2[4] = {ha.x, ha.y, hb.x, hb.y};
        float4 w0 = *(const float4*)(w_t + k * WTP + gbase);
        float4 w1 = *(const float4*)(w_t + k * WTP + gbase + 4);
        float wv[6] = {w0.x, w0.y, w0.z, w0.w, w1.x, w1.y};
#pragma unroll
        for (int g = 0; g < 6; g++) {
            ull wp = pack2(wv[g]);
#pragma unroll
            for (int p = 0; p < 4; p++) fma2(acc[p][g], wp, h2[p]);
        }
    }
    float* pb = part + (ks * 16 + tile) * 48;
#pragma unroll
    for (int g = 0; g < 6; g++) {
        float l0, h0v, l1, h1, l2, h2v, l3, h3;
        unpack2(acc[0][g], l0, h0v); unpack2(acc[1][g], l1, h1);
        unpack2(acc[2][g], l2, h2v); unpack2(acc[3][g], l3, h3);
        *(float4*)(pb + g * 8)     = make_float4(l0, h0v, l1, h1);
        *(float4*)(pb + g * 8 + 4) = make_float4(l2, h2v, l3, h3);
    }
    __syncthreads();

    int b = tid & 63, jg = tid >> 6;
    int bgr = b >> 3, bi = b & 7;
    int tR = bgr * 2 + 0, iR = jg * 8 + bi;
    int tZ, iZ;
    if (jg < 2) { tZ = bgr * 2 + 0; iZ = (4 + jg) * 8 + bi; }
    else        { tZ = bgr * 2 + 1; iZ = (jg - 2) * 8 + bi; }
    int tN = bgr * 2 + 1, iN = (2 + jg) * 8 + bi;
    float sr = 0.f, sz = 0.f, sn = 0.f;
#pragma unroll
    for (int s = 0; s < 16; s++) {
        sr += part[(s * 16 + tR) * 48 + iR];
        sz += part[(s * 16 + tZ) * 48 + iZ];
        sn += part[(s * 16 + tN) * 48 + iN];
    }
    int j = j0 + jg;
    sr += b_hh[j]; sz += b_hh[HID + j]; sn += b_hh[2 * HID + j];
    const float* xrow = g_xg + ((long)b * NSTEP + t) * G3;
    float r_ = 1.f / (1.f + expf(-(xrow[j] + sr)));
    float z_ = 1.f / (1.f + expf(-(xrow[HID + j] + sz)));
    float n_ = tanhf(xrow[2 * HID + j] + r_ * sn);
    float hp = h_t[j * HTP + b];
    float hn = (1.f - z_) * n_ + z_ * hp;
    h_out[j * B_SZ + b] = hn;
    hs[((long)b * NSTEP + t) * HID + j] = hn;
}

// ---------------- classifier: mma.sync bf16 3-split, cp.async pipelined --
// CTA 128x128, 8 warps (2Mx4N), warp 64x32. Double-buffered 2x64KB smem.
#define CLS_SMEM 131072
#define BUF_STRIDE 65536
#define OA_H 0
#define OA_L 16384
#define OB_H 32768
#define OB_L 49152

__global__ void __launch_bounds__(256, 1)
cls_mma3(const float* __restrict__ bias, float* __restrict__ out) {
    extern __shared__ char csm[];
    uint32_t sb = s2u(csm);
    int tid = threadIdx.x;
    int wid = tid >> 5, l = tid & 31;
    int wm = wid >> 2, wn = wid & 3;
    int mtile = blockIdx.y * 128;
    int ntile = blockIdx.x * 128;

    float d[4][4][4];
#pragma unroll
    for (int i = 0; i < 4; i++)
#pragma unroll
        for (int j = 0; j < 4; j++)
#pragma unroll
            for (int k = 0; k < 4; k++) d[i][j][k] = 0.f;

    // per-lane ldmatrix coords
    int rA = l & 15, kA = (l >> 4) * 8;
    int rB = l & 7,  kB = ((l >> 3) & 1) * 8;

    // per-thread cp.async coords (16 x 16B per chunk)
    // id = tid + q*256; seg = id>>10; r = (id>>3)&127; c16 = id&7
#define PREFETCH(c)                                                            \
    do {                                                                       \
        int kc_ = (c) * 64;                                                    \
        uint32_t bufb_ = sb + ((c) & 1) * BUF_STRIDE;                          \
        _Pragma("unroll")                                                      \
        for (int q = 0; q < 16; q++) {                                         \
            int id = tid + q * 256;                                            \
            int seg = id >> 10;                                                \
            int r = (id >> 3) & 127;                                           \
            int c16 = id & 7;                                                  \
            const __nv_bfloat16* src;                                          \
            if (seg == 0)      src = g_Ah + (long)(mtile + r) * HID;           \
            else if (seg == 1) src = g_Al + (long)(mtile + r) * HID;           \
            else if (seg == 2) src = g_Bh + (long)(ntile + r) * HID;           \
            else               src = g_Bl + (long)(ntile + r) * HID;           \
            uint32_t dst = bufb_ + seg * 16384 +                               \
                           swz((uint32_t)(r * 128 + c16 * 16));                \
            asm volatile("cp.async.ca.shared.global [%0], [%1], 16;"           \
                         :: "r"(dst), "l"(src + kc_ + c16 * 8) : "memory");    \
        }                                                                      \
        asm volatile("cp.async.commit_group;" ::: "memory");                   \
    } while (0)

    PREFETCH(0);
    for (int c = 0; c < 8; c++) {
        if (c < 7) {
            PREFETCH(c + 1);
            asm volatile("cp.async.wait_group 1;" ::: "memory");
        } else {
            asm volatile("cp.async.wait_group 0;" ::: "memory");
        }
        __syncthreads();
        uint32_t bufb = sb + (c & 1) * BUF_STRIDE;

#pragma unroll
        for (int kst = 0; kst < 4; kst++) {
            uint32_t ah[4][4], al[4][4], bh[4][2], bl[4][2];
#pragma unroll
            for (int nt = 0; nt < 4; nt++) {
                int row = wn * 32 + nt * 8 + rB;
                uint32_t off = swz((uint32_t)(row * 128 + (kst * 16 + kB) * 2));
                asm volatile(
                    "ldmatrix.sync.aligned.m8n8.x2.shared.b16 {%0,%1}, [%2];"
                    : "=r"(bh[nt][0]), "=r"(bh[nt][1]) : "r"(bufb + OB_H + off));
                asm volatile(
                    "ldmatrix.sync.aligned.m8n8.x2.shared.b16 {%0,%1}, [%2];"
                    : "=r"(bl[nt][0]), "=r"(bl[nt][1]) : "r"(bufb + OB_L + off));
            }
#pragma unroll
            for (int mt = 0; mt < 4; mt++) {
                int row = wm * 64 + mt * 16 + rA;
                uint32_t off = swz((uint32_t)(row * 128 + (kst * 16 + kA) * 2));
                asm volatile(
                    "ldmatrix.sync.aligned.m8n8.x4.shared.b16 {%0,%1,%2,%3}, [%4];"
                    : "=r"(ah[mt][0]), "=r"(ah[mt][1]),
                      "=r"(ah[mt][2]), "=r"(ah[mt][3]) : "r"(bufb + OA_H + off));
                asm volatile(
                    "ldmatrix.sync.aligned.m8n8.x4.shared.b16 {%0,%1,%2,%3}, [%4];"
                    : "=r"(al[mt][0]), "=r"(al[mt][1]),
                      "=r"(al[mt][2]), "=r"(al[mt][3]) : "r"(bufb + OA_L + off));
            }
#pragma unroll
            for (int mt = 0; mt < 4; mt++) {
#pragma unroll
                for (int nt = 0; nt < 4; nt++) {
                    asm volatile(
                        "mma.sync.aligned.m16n8k16.row.col.f32.bf16.bf16.f32 "
                        "{%0,%1,%2,%3}, {%4,%5,%6,%7}, {%8,%9}, {%0,%1,%2,%3};"
                        : "+f"(d[mt][nt][0]), "+f"(d[mt][nt][1]),
                          "+f"(d[mt][nt][2]), "+f"(d[mt][nt][3])
                        : "r"(ah[mt][0]), "r"(ah[mt][1]), "r"(ah[mt][2]), "r"(ah[mt][3]),
                          "r"(bh[nt][0]), "r"(bh[nt][1]));
                    asm volatile(
                        "mma.sync.aligned.m16n8k16.row.col.f32.bf16.bf16.f32 "
                        "{%0,%1,%2,%3}, {%4,%5,%6,%7}, {%8,%9}, {%0,%1,%2,%3};"
                        : "+f"(d[mt][nt][0]), "+f"(d[mt][nt][1]),
                          "+f"(d[mt][nt][2]), "+f"(d[mt][nt][3])
                        : "r"(ah[mt][0]), "r"(ah[mt][1]), "r"(ah[mt][2]), "r"(ah[mt][3]),
                          "r"(bl[nt][0]), "r"(bl[nt][1]));
                    asm volatile(
                        "mma.sync.aligned.m16n8k16.row.col.f32.bf16.bf16.f32 "
                        "{%0,%1,%2,%3}, {%4,%5,%6,%7}, {%8,%9}, {%0,%1,%2,%3};"
                        : "+f"(d[mt][nt][0]), "+f"(d[mt][nt][1]),
                          "+f"(d[mt][nt][2]), "+f"(d[mt][nt][3])
                        : "r"(al[mt][0]), "r"(al[mt][1]), "r"(al[mt][2]), "r"(al[mt][3]),
                          "r"(bh[nt][0]), "r"(bh[nt][1]));
                }
            }
        }
        __syncthreads();
    }

    // epilogue
    int rbase = mtile + wm * 64 + (l >> 2);
    int cbase = ntile + wn * 32 + (l & 3) * 2;
#pragma unroll
    for (int nt = 0; nt < 4; nt++) {
        int col = cbase + nt * 8;
        float b0 = bias[col], b1 = bias[col + 1];
#pragma unroll
        for (int mt = 0; mt < 4; mt++) {
            int r0 = rbase + mt * 16;
            if (r0 < MROWS) {
                float2 v = make_float2(d[mt][nt][0] + b0, d[mt][nt][1] + b1);
                *(float2*)(out + (long)r0 * VOCAB + col) = v;
            }
            if (r0 + 8 < MROWS) {
                float2 v = make_float2(d[mt][nt][2] + b0, d[mt][nt][3] + b1);
                *(float2*)(out + (long)(r0 + 8) * VOCAB + col) = v;
            }
        }
    }
}

// ---------------- launch ----------------
extern "C" void kernel_launch(void* const* d_in, const int* in_sizes, int n_in,
                              void* d_out, int out_size) {
    const float* word_embs = (const float*)d_in[0];
    const float* vis       = (const float*)d_in[1];
    const float* tof       = (const float*)d_in[2];
    const float* W_map     = (const float*)d_in[4];
    const float* b_map     = (const float*)d_in[5];
    const float* w_ih      = (const float*)d_in[6];
    const float* w_hh      = (const float*)d_in[7];
    const float* b_ih      = (const float*)d_in[8];
    const float* b_hh      = (const float*)d_in[9];
    const float* W_cls     = (const float*)d_in[10];
    const float* b_cls     = (const float*)d_in[11];
    float* out = (float*)d_out;

    float *wihT, *xg, *ht, *hs;
    cudaGetSymbolAddress((void**)&wihT, g_wihT);
    cudaGetSymbolAddress((void**)&xg,   g_xg);
    cudaGetSymbolAddress((void**)&ht,   g_ht);
    cudaGetSymbolAddress((void**)&hs,   g_hs);

    cudaFuncSetAttribute(gru_step3, cudaFuncAttributeMaxDynamicSharedMemorySize,
                         GRU_SMEM);
    cudaFuncSetAttribute(cls_mma3, cudaFuncAttributeMaxDynamicSharedMemorySize,
                         CLS_SMEM);

    transpose_wih<<<(EMB * G3 + 255) / 256, 256>>>(w_ih);
    h0_kernel<<<64, 256>>>(vis, tof, W_map, b_map, ht);
    {
        dim3 grid(G3 / 128, (MROWS + 127) / 128);
        gemm128<<<grid, 256>>>(word_embs, wihT, b_ih, xg, MROWS, G3, EMB);
    }
    {
        dim3 grid(VOCAB / 32, HID / 32);
        convert_W<<<grid, dim3(32, 8)>>>(W_cls);
    }
    for (int t = 0; t < NSTEP; t++) {
        const float* hin = ht + (t & 1) * (HID * B_SZ);
        float* hout      = ht + ((t + 1) & 1) * (HID * B_SZ);
        gru_step3<<<128, 256, GRU_SMEM>>>(hin, hout, hs, w_hh, b_hh, t);
    }
    convert_A<<<(MPAD * HID / 4) / 256, 256>>>(hs);
    {
        dim3 grid(VOCAB / 128, MPAD / 128);
        cls_mma3<<<grid, 256, CLS_SMEM>>>(b_cls, out);
    }
    (void)in_sizes; (void)n_in; (void)out_size;
}